// round 2
// baseline (speedup 1.0000x reference)
#include <cuda_runtime.h>
#include <cstdint>

// ItemCodeDPQ: out[b,s,m*16+d] = centroids[m, clamp(item_codes[input_ids[b,s], m],0,255), d]
//              zeroed where input_ids[b,s] == 0.
// NOTE: input_ids arrive as int32 (JAX x64-disabled downcasts the declared int64).
// Strategy: stage full centroid table (8*256*16 fp32 = 128KB) in shared memory,
// one warp per token, lane i writes output float4 i (512B/token coalesced).

#define CENT_FLOATS (8 * 256 * 16)   // 32768 floats = 131072 bytes
#define CENT_F4 (CENT_FLOATS / 4)    // 8192 float4

__global__ void __launch_bounds__(512, 1)
itemcode_dpq_kernel(const int* __restrict__ input_ids,
                    const int* __restrict__ item_codes,
                    const float4* __restrict__ centroids4,
                    float4* __restrict__ out4,
                    int ntok)
{
    extern __shared__ float4 s_cent[];   // [8192] float4 = full centroid table

    // Cooperative load of centroid table into smem (16 float4 per thread)
    #pragma unroll 4
    for (int i = threadIdx.x; i < CENT_F4; i += 512) {
        s_cent[i] = centroids4[i];
    }
    __syncthreads();

    const int lane = threadIdx.x & 31;
    const int sub  = lane >> 2;          // 0..7 : which sub-codebook this lane serves
    const int part = lane & 3;           // 0..3 : which float4 within the 16-float sub-emb

    const int warp  = (int)((blockIdx.x * blockDim.x + threadIdx.x) >> 5);
    const int nwarp = (int)((gridDim.x * blockDim.x) >> 5);

    for (int t = warp; t < ntok; t += nwarp) {
        int id = input_ids[t];           // uniform across warp -> single sector

        // lanes 0..7 fetch the 8 codes for this item (one coalesced 32B read)
        int code = 0;
        if (lane < 8) {
            code = item_codes[(size_t)id * 8 + lane];
            code = min(max(code, 0), 255);
        }
        code = __shfl_sync(0xffffffffu, code, sub);

        float4 v;
        if (id == 0) {
            v = make_float4(0.f, 0.f, 0.f, 0.f);
        } else {
            // centroids[sub][code][part*4 .. part*4+3]
            v = s_cent[(sub * 256 + code) * 4 + part];
        }
        out4[(size_t)t * 32 + lane] = v;
    }
}

extern "C" void kernel_launch(void* const* d_in, const int* in_sizes, int n_in,
                              void* d_out, int out_size)
{
    const int*    input_ids  = (const int*)d_in[0];     // (1024,200) int32
    const int*    item_codes = (const int*)d_in[1];     // (1e6, 8) int32
    const float4* centroids  = (const float4*)d_in[2];  // (8,256,16) fp32
    float4*       out        = (float4*)d_out;          // (1024,200,128) fp32

    const int ntok = in_sizes[0];   // 204800

    // 131072 bytes dynamic smem requires opt-in above 48KB default.
    static_assert(CENT_F4 * sizeof(float4) == 131072, "centroid table size");
    cudaFuncSetAttribute(itemcode_dpq_kernel,
                         cudaFuncAttributeMaxDynamicSharedMemorySize, 131072);

    int nsm = 148;
    cudaDeviceGetAttribute(&nsm, cudaDevAttrMultiProcessorCount, 0);

    itemcode_dpq_kernel<<<nsm, 512, 131072>>>(input_ids, item_codes, centroids,
                                              out, ntok);
}

// round 3
// speedup vs baseline: 1.7485x; 1.7485x over previous
#include <cuda_runtime.h>
#include <cstdint>

// ItemCodeDPQ: out[b,s,m*16+d] = centroids[m, clamp(item_codes[input_ids[b,s], m],0,255), d]
//              zeroed where input_ids[b,s] == 0.  input_ids arrive as int32.
//
// R3: no shared memory (128KB centroid table lives in L1, 228KB, per-SM),
// 4 tokens per warp iteration for MLP, full occupancy.

__global__ void __launch_bounds__(256)
itemcode_dpq_kernel(const int* __restrict__ input_ids,
                    const int* __restrict__ item_codes,
                    const float4* __restrict__ centroids4,
                    float4* __restrict__ out4,
                    int ntok)
{
    const int lane = threadIdx.x & 31;
    const int sub  = lane >> 2;          // 0..7 : sub-codebook this lane serves
    const int part = lane & 3;           // 0..3 : float4 within 16-float sub-emb

    const int warp = (int)((blockIdx.x * blockDim.x + threadIdx.x) >> 5);
    const int t0   = warp * 4;
    if (t0 >= ntok) return;

    // ---- load 4 ids (uniform broadcast loads) ----
    int id[4];
    #pragma unroll
    for (int j = 0; j < 4; j++) {
        int t = t0 + j;
        id[j] = (t < ntok) ? input_ids[t] : 0;
    }

    // ---- one coalesced 32-lane code fetch covering all 4 tokens ----
    // group g = lane>>3 serves token g; lane&7 = code byte index
    int myc = __ldg(&item_codes[(size_t)id[lane >> 3] * 8 + (lane & 7)]);
    myc = min(max(myc, 0), 255);

    // ---- 4 independent gathers + 4 independent coalesced 512B stores ----
    #pragma unroll
    for (int j = 0; j < 4; j++) {
        int t = t0 + j;
        if (t >= ntok) break;
        int code = __shfl_sync(0xffffffffu, myc, j * 8 + sub);
        float4 v;
        if (id[j] == 0) {
            v = make_float4(0.f, 0.f, 0.f, 0.f);
        } else {
            v = __ldg(&centroids4[(sub * 256 + code) * 4 + part]);
        }
        out4[(size_t)t * 32 + lane] = v;
    }
}

extern "C" void kernel_launch(void* const* d_in, const int* in_sizes, int n_in,
                              void* d_out, int out_size)
{
    const int*    input_ids  = (const int*)d_in[0];     // (1024,200) int32
    const int*    item_codes = (const int*)d_in[1];     // (1e6, 8) int32
    const float4* centroids  = (const float4*)d_in[2];  // (8,256,16) fp32
    float4*       out        = (float4*)d_out;          // (1024,200,128) fp32

    const int ntok = in_sizes[0];   // 204800

    // 4 tokens per warp, 8 warps per 256-thread CTA
    int warps = (ntok + 3) / 4;
    int ctas  = (warps + 7) / 8;
    itemcode_dpq_kernel<<<ctas, 256>>>(input_ids, item_codes, centroids,
                                       out, ntok);
}

// round 4
// speedup vs baseline: 2.0764x; 1.1875x over previous
#include <cuda_runtime.h>
#include <cstdint>

// ItemCodeDPQ: out[b,s,m*16+d] = centroids[m, clamp(item_codes[input_ids[b,s], m],0,255), d]
//              zeroed where input_ids[b,s] == 0.  input_ids arrive as int32.
//
// R4: 8 tokens per warp. One coalesced id load, two coalesced code fetches,
// 8 register-staged independent gathers (L1-resident 128KB centroid table),
// 8 streaming 512B stores (__stcs: keep item_codes L2-resident).

__global__ void __launch_bounds__(256)
itemcode_dpq_kernel(const int* __restrict__ input_ids,
                    const int* __restrict__ item_codes,
                    const float4* __restrict__ centroids4,
                    float4* __restrict__ out4,
                    int ntok)
{
    const int lane = threadIdx.x & 31;
    const int sub  = lane >> 2;          // 0..7 : sub-codebook this lane serves
    const int part = lane & 3;           // 0..3 : float4 within 16-float sub-emb

    const int warp = (int)((blockIdx.x * blockDim.x + threadIdx.x) >> 5);
    const int t0   = warp * 8;
    if (t0 >= ntok) return;

    // ---- one coalesced 32B id load (lanes 0..7), broadcast to all lanes ----
    int myid = 0;
    if (lane < 8 && (t0 + lane) < ntok) myid = input_ids[t0 + lane];

    int id[8];
    #pragma unroll
    for (int j = 0; j < 8; j++) id[j] = __shfl_sync(0xffffffffu, myid, j);

    // ---- two coalesced code fetches: 64 codes for 8 tokens ----
    const int g = lane >> 3;             // 0..3 : token within half
    const int b = lane & 7;              // 0..7 : code byte index
    int c0 = __ldg(&item_codes[(size_t)id[g]     * 8 + b]);   // tokens 0..3
    int c1 = __ldg(&item_codes[(size_t)id[4 + g] * 8 + b]);   // tokens 4..7
    c0 = min(max(c0, 0), 255);
    c1 = min(max(c1, 0), 255);

    // ---- 8 independent gathers staged into registers (MLP=8) ----
    float4 v[8];
    #pragma unroll
    for (int j = 0; j < 8; j++) {
        if (t0 + j >= ntok) { v[j] = make_float4(0.f, 0.f, 0.f, 0.f); continue; }
        int code = __shfl_sync(0xffffffffu, (j < 4) ? c0 : c1, (j & 3) * 8 + sub);
        if (id[j] == 0) {
            v[j] = make_float4(0.f, 0.f, 0.f, 0.f);
        } else {
            v[j] = __ldg(&centroids4[(sub * 256 + code) * 4 + part]);
        }
    }

    // ---- 8 independent streaming 512B stores ----
    #pragma unroll
    for (int j = 0; j < 8; j++) {
        int t = t0 + j;
        if (t >= ntok) break;
        __stcs(&out4[(size_t)t * 32 + lane], v[j]);
    }
}

extern "C" void kernel_launch(void* const* d_in, const int* in_sizes, int n_in,
                              void* d_out, int out_size)
{
    const int*    input_ids  = (const int*)d_in[0];     // (1024,200) int32
    const int*    item_codes = (const int*)d_in[1];     // (1e6, 8) int32
    const float4* centroids  = (const float4*)d_in[2];  // (8,256,16) fp32
    float4*       out        = (float4*)d_out;          // (1024,200,128) fp32

    const int ntok = in_sizes[0];   // 204800

    // 8 tokens per warp, 8 warps per 256-thread CTA => 64 tokens per CTA
    int warps = (ntok + 7) / 8;
    int ctas  = (warps + 7) / 8;
    itemcode_dpq_kernel<<<ctas, 256>>>(input_ids, item_codes, centroids,
                                       out, ntok);
}

// round 5
// speedup vs baseline: 2.1449x; 1.0330x over previous
#include <cuda_runtime.h>
#include <cstdint>

// ItemCodeDPQ: out[b,s,m*16+d] = centroids[m, clamp(item_codes[input_ids[b,s], m],0,255), d]
//              zeroed where input_ids[b,s] == 0.  input_ids arrive as int32.
//
// R5: 16 tokens per warp. One coalesced id load (lanes 0..15), four coalesced
// code fetches, gather->store immediately per token (no register staging:
// ptxas overlaps the independent LDGs; keeps regs low for high occupancy).
// 32-bit address math throughout. __stcs streaming stores keep item_codes
// (32MB) resident in L2 (126MB).

__global__ void __launch_bounds__(256)
itemcode_dpq_kernel(const int* __restrict__ input_ids,
                    const int* __restrict__ item_codes,
                    const float4* __restrict__ centroids4,
                    float4* __restrict__ out4,
                    int ntok)
{
    const unsigned lane = threadIdx.x & 31u;
    const unsigned sub  = lane >> 2;          // 0..7 : sub-codebook this lane serves
    const unsigned part = lane & 3u;          // 0..3 : float4 within 16-float sub-emb

    const unsigned warp = (blockIdx.x * blockDim.x + threadIdx.x) >> 5;
    const unsigned t0   = warp * 16u;
    if (t0 >= (unsigned)ntok) return;
    // grid is sized so each full warp has 16 valid tokens (ntok = 204800 = 16*12800)

    // ---- one coalesced 64B id load (lanes 0..15) ----
    int myid = 0;
    if (lane < 16u) myid = input_ids[t0 + lane];

    // ---- four coalesced code fetches: 128 codes for 16 tokens ----
    const unsigned g = lane >> 3;             // 0..3 : token within quad
    const unsigned b = lane & 7u;             // 0..7 : code byte index
    int c[4];
    #pragma unroll
    for (int r = 0; r < 4; r++) {
        unsigned idg = (unsigned)__shfl_sync(0xffffffffu, myid, r * 4 + g);
        int cc = __ldg(&item_codes[idg * 8u + b]);
        c[r] = min(max(cc, 0), 255);
    }

    // ---- 16 tokens: gather (L1-resident 128KB table) -> streaming store ----
    #pragma unroll
    for (int j = 0; j < 16; j++) {
        int idj  = __shfl_sync(0xffffffffu, myid, j);
        int code = __shfl_sync(0xffffffffu, c[j >> 2], (j & 3) * 8 + sub);
        float4 v;
        if (idj == 0) {
            v = make_float4(0.f, 0.f, 0.f, 0.f);
        } else {
            v = __ldg(&centroids4[(sub * 256u + (unsigned)code) * 4u + part]);
        }
        __stcs(&out4[(t0 + (unsigned)j) * 32u + lane], v);
    }
}

extern "C" void kernel_launch(void* const* d_in, const int* in_sizes, int n_in,
                              void* d_out, int out_size)
{
    const int*    input_ids  = (const int*)d_in[0];     // (1024,200) int32
    const int*    item_codes = (const int*)d_in[1];     // (1e6, 8) int32
    const float4* centroids  = (const float4*)d_in[2];  // (8,256,16) fp32
    float4*       out        = (float4*)d_out;          // (1024,200,128) fp32

    const int ntok = in_sizes[0];   // 204800 (divisible by 16)

    // 16 tokens per warp, 8 warps per 256-thread CTA => 128 tokens per CTA
    int warps = (ntok + 15) / 16;
    int ctas  = (warps + 7) / 8;
    itemcode_dpq_kernel<<<ctas, 256>>>(input_ids, item_codes, centroids,
                                       out, ntok);
}

// round 6
// speedup vs baseline: 2.2790x; 1.0625x over previous
#include <cuda_runtime.h>
#include <cstdint>

// ItemCodeDPQ: out[b,s,m*16+d] = centroids[m, clamp(item_codes[input_ids[b,s], m],0,255), d]
//              zeroed where input_ids[b,s] == 0.  input_ids arrive as int32.
//
// R6: shuffle-free. 16 tokens/warp; per token every lane loads the (uniform)
// id directly, then its own code word directly (4 lanes/sub broadcast-merge:
// warp still touches one 32B sector per token), then gathers its float4 from
// the L1-resident 128KB centroid table and streams out 512B/token.
// 16 independent LDG->LDG->LDG->STG chains per warp; no SHFL anywhere.

__global__ void __launch_bounds__(256)
itemcode_dpq_kernel(const int* __restrict__ input_ids,
                    const int* __restrict__ item_codes,
                    const float4* __restrict__ centroids4,
                    float4* __restrict__ out4,
                    int ntok)
{
    const unsigned lane = threadIdx.x & 31u;
    const unsigned sub  = lane >> 2;          // 0..7 : sub-codebook this lane serves
    const unsigned part = lane & 3u;          // 0..3 : float4 within 16-float sub-emb

    const unsigned warp = (blockIdx.x * blockDim.x + threadIdx.x) >> 5;
    const unsigned t0   = warp * 16u;
    if (t0 >= (unsigned)ntok) return;         // ntok = 204800 is divisible by 16

    #pragma unroll
    for (int j = 0; j < 16; j++) {
        const unsigned t = t0 + (unsigned)j;
        // uniform load: whole warp reads one word (16 of these share 1 line)
        const unsigned id = (unsigned)__ldg(&input_ids[t]);
        // per-lane code load: 8 distinct words per warp = one 32B sector
        int code = __ldg(&item_codes[id * 8u + sub]);
        code = min(max(code, 0), 255);

        float4 v;
        if (id == 0u) {
            v = make_float4(0.f, 0.f, 0.f, 0.f);
        } else {
            v = __ldg(&centroids4[(sub * 256u + (unsigned)code) * 4u + part]);
        }
        __stcs(&out4[t * 32u + lane], v);
    }
}

extern "C" void kernel_launch(void* const* d_in, const int* in_sizes, int n_in,
                              void* d_out, int out_size)
{
    const int*    input_ids  = (const int*)d_in[0];     // (1024,200) int32
    const int*    item_codes = (const int*)d_in[1];     // (1e6, 8) int32
    const float4* centroids  = (const float4*)d_in[2];  // (8,256,16) fp32
    float4*       out        = (float4*)d_out;          // (1024,200,128) fp32

    const int ntok = in_sizes[0];   // 204800

    // 16 tokens per warp, 8 warps per 256-thread CTA => 128 tokens per CTA
    int warps = (ntok + 15) / 16;
    int ctas  = (warps + 7) / 8;
    itemcode_dpq_kernel<<<ctas, 256>>>(input_ids, item_codes, centroids,
                                       out, ntok);
}